// round 16
// baseline (speedup 1.0000x reference)
#include <cuda_runtime.h>
#include <cuda_fp16.h>
#include <mma.h>
#include <cstdint>

#define EMBED 1024
#define NHEADS 16
#define HDIM 64
#define BATCH 2
#define SEQ 2048
#define MTOT 4096

// fp16 scratch (device globals -- no runtime allocation allowed)
__device__ __half g_hXq[MTOT * EMBED];
__device__ __half g_hXk[MTOT * EMBED];
__device__ __half g_hXv[MTOT * EMBED];
__device__ __half g_hWq[EMBED * EMBED];
__device__ __half g_hWk[EMBED * EMBED];
__device__ __half g_hWv[EMBED * EMBED];
__device__ __half g_hWo[EMBED * EMBED];
__device__ __half g_hQ[MTOT * EMBED];
__device__ __half g_hK[MTOT * EMBED];
__device__ __half g_hV[MTOT * EMBED];
__device__ __half g_hCTX[MTOT * EMBED];

__device__ __forceinline__ void cp16(uint32_t dst, const void* src) {
    asm volatile("cp.async.cg.shared.global [%0], [%1], 16;\n"
                 :: "r"(dst), "l"(src));
}
#define CP_COMMIT() asm volatile("cp.async.commit_group;\n")
#define CP_WAIT(n)  asm volatile("cp.async.wait_group %0;\n" :: "n"(n))

__device__ __forceinline__ unsigned pack_h2(float a, float b) {
    __half2 h = __floats2half2_rn(a, b);
    return *(unsigned*)&h;
}

__device__ __forceinline__ float ex2(float x) {
    float r;
    asm("ex2.approx.f32 %0, %1;" : "=f"(r) : "f"(x));
    return r;
}

// ---- raw mma helpers ----
__device__ __forceinline__ void ldsm_x4(uint32_t* r, uint32_t addr) {
    asm volatile("ldmatrix.sync.aligned.m8n8.x4.shared.b16 {%0,%1,%2,%3}, [%4];"
        : "=r"(r[0]), "=r"(r[1]), "=r"(r[2]), "=r"(r[3]) : "r"(addr));
}
__device__ __forceinline__ void ldsm_x4_t(uint32_t* r, uint32_t addr) {
    asm volatile("ldmatrix.sync.aligned.m8n8.x4.trans.shared.b16 {%0,%1,%2,%3}, [%4];"
        : "=r"(r[0]), "=r"(r[1]), "=r"(r[2]), "=r"(r[3]) : "r"(addr));
}
__device__ __forceinline__ void mma16816(float* c, const uint32_t* a,
                                         uint32_t b0, uint32_t b1) {
    asm volatile(
        "mma.sync.aligned.m16n8k16.row.col.f32.f16.f16.f32 "
        "{%0,%1,%2,%3}, {%4,%5,%6,%7}, {%8,%9}, {%0,%1,%2,%3};"
        : "+f"(c[0]), "+f"(c[1]), "+f"(c[2]), "+f"(c[3])
        : "r"(a[0]), "r"(a[1]), "r"(a[2]), "r"(a[3]), "r"(b0), "r"(b1));
}

#define ALD 72
__device__ __forceinline__ uint32_t ldsm_addr(uint32_t base, int row0, int col0,
                                              int lane) {
    int g = lane >> 3, l = lane & 7;
    int r = row0 + ((g & 1) << 3) + l;
    int c = col0 + ((g >> 1) << 3);
    return base + (uint32_t)(r * ALD + c) * 2;
}

// ---------------------------------------------------------------------------
// fp32 -> fp16 conversion of inputs + weights (2 float4 per thread)
// ---------------------------------------------------------------------------
#define X4 1048576
#define W4 262144

__global__ void cvt_all(
    const float* __restrict__ xq, const float* __restrict__ xk,
    const float* __restrict__ xv,
    const float* __restrict__ wq, const float* __restrict__ wk,
    const float* __restrict__ wv, const float* __restrict__ wo,
    __half* hxq, __half* hxk, __half* hxv,
    __half* hwq, __half* hwk, __half* hwv, __half* hwo)
{
    int i0 = (blockIdx.x * blockDim.x + threadIdx.x) * 2;
    const float* src; __half* dst; int off;
    if      (i0 < X4)            { src = xq; dst = hxq; off = i0; }
    else if (i0 < 2 * X4)        { src = xk; dst = hxk; off = i0 - X4; }
    else if (i0 < 3 * X4)        { src = xv; dst = hxv; off = i0 - 2 * X4; }
    else if (i0 < 3 * X4 + W4)   { src = wq; dst = hwq; off = i0 - 3 * X4; }
    else if (i0 < 3 * X4 + 2*W4) { src = wk; dst = hwk; off = i0 - 3*X4 - W4; }
    else if (i0 < 3 * X4 + 3*W4) { src = wv; dst = hwv; off = i0 - 3*X4 - 2*W4; }
    else                         { src = wo; dst = hwo; off = i0 - 3*X4 - 3*W4; }
#pragma unroll
    for (int t = 0; t < 2; t++) {
        float4 v = ((const float4*)src)[off + t];
        uint2 u;
        u.x = pack_h2(v.x, v.y); u.y = pack_h2(v.z, v.w);
        ((uint2*)dst)[off + t] = u;
    }
}

// ---------------------------------------------------------------------------
// GEMM v5 (raw mma): 128x128 block tile, 8 warps (4m x 2n) of 32x64.
// 256 threads, K-tile 64, 3-stage cp.async ring, 1 sync/iter.
// NO minCTA clamp -- ptxas free to use ~100 regs (2 CTAs/SM).
// ---------------------------------------------------------------------------
#define GTILE (128 * ALD)
#define GSTAGE (2 * GTILE)
#define GEMM_SMEM (3 * GSTAGE * 2)       // 110592 B

__device__ __forceinline__ void gemm_fill(
    const __half* __restrict__ A, const __half* __restrict__ W,
    int m0, int n0, uint32_t sb, int s, int kt, int tid)
{
    int so = s * GSTAGE;
#pragma unroll
    for (int i = 0; i < 4; i++) {
        int idx = tid + i * 256;
        int row = idx >> 3;
        int c8  = (idx & 7) * 8;
        cp16(sb + (uint32_t)(so + row * ALD + c8) * 2,
             &A[(size_t)(m0 + row) * 1024 + kt + c8]);
        cp16(sb + (uint32_t)(so + GTILE + row * ALD + c8) * 2,
             &W[(size_t)(n0 + row) * 1024 + kt + c8]);
    }
    CP_COMMIT();
}

// acc[mi][nj][4]: mi = m16 tile (0..1), nj = n8 tile (0..7)
__device__ __forceinline__ void gemm_mainloop_raw(
    const __half* __restrict__ A, const __half* __restrict__ W,
    int m0, int n0, uint32_t sb, float acc[2][8][4])
{
    const int tid  = threadIdx.x;
    const int warp = tid >> 5;
    const int lane = tid & 31;
    const int wm   = warp >> 1;          // 0..3 -> rows wm*32
    const int wn   = warp & 1;           // 0..1 -> cols wn*64

    gemm_fill(A, W, m0, n0, sb, 0, 0, tid);
    gemm_fill(A, W, m0, n0, sb, 1, 64, tid);

    for (int t = 0; t < 16; t++) {
        if (t < 15) { CP_WAIT(1); } else { CP_WAIT(0); }
        __syncthreads();
        if (t + 2 <= 15)
            gemm_fill(A, W, m0, n0, sb, (t + 2) % 3, (t + 2) * 64, tid);

        const uint32_t As = sb + (uint32_t)((t % 3) * GSTAGE) * 2;
        const uint32_t Bs = As + (uint32_t)GTILE * 2;

#pragma unroll
        for (int kk = 0; kk < 4; kk++) {
            uint32_t a[2][4];
#pragma unroll
            for (int mi = 0; mi < 2; mi++)
                ldsm_x4(a[mi], ldsm_addr(As, wm * 32 + mi * 16, kk * 16, lane));
#pragma unroll
            for (int nj2 = 0; nj2 < 4; nj2++) {
                uint32_t bf[4];
                ldsm_x4(bf, ldsm_addr(Bs, wn * 64 + nj2 * 16, kk * 16, lane));
#pragma unroll
                for (int mi = 0; mi < 2; mi++) {
                    mma16816(acc[mi][2 * nj2],     a[mi], bf[0], bf[2]);
                    mma16816(acc[mi][2 * nj2 + 1], a[mi], bf[1], bf[3]);
                }
            }
        }
    }
}

// Projections: half in, half out (Q pre-scaled by 0.125*log2e)
__global__ __launch_bounds__(256) void proj3_kernel(
    const __half* __restrict__ xq, const __half* __restrict__ xk,
    const __half* __restrict__ xv,
    const __half* __restrict__ wq, const __half* __restrict__ wk,
    const __half* __restrict__ wv,
    __half* q, __half* k, __half* v)
{
    extern __shared__ __half gsm[];
    const __half* A; const __half* W; __half* C; float scale;
    if (blockIdx.z == 0)      { A = xq; W = wq; C = q; scale = 0.125f * 1.44269504f; }
    else if (blockIdx.z == 1) { A = xk; W = wk; C = k; scale = 1.0f; }
    else                      { A = xv; W = wv; C = v; scale = 1.0f; }
    const int m0 = blockIdx.y * 128, n0 = blockIdx.x * 128;
    const int warp = threadIdx.x >> 5, lane = threadIdx.x & 31;
    const int wm = warp >> 1, wn = warp & 1;
    const int qr = lane >> 2, qc = lane & 3;
    uint32_t sb = (uint32_t)__cvta_generic_to_shared(gsm);

    float acc[2][8][4];
#pragma unroll
    for (int mi = 0; mi < 2; mi++)
#pragma unroll
        for (int nj = 0; nj < 8; nj++)
#pragma unroll
            for (int e = 0; e < 4; e++) acc[mi][nj][e] = 0.0f;

    gemm_mainloop_raw(A, W, m0, n0, sb, acc);

    // direct global epilogue: u32 fp16-pair stores
#pragma unroll
    for (int mi = 0; mi < 2; mi++) {
        const size_t r0 = (size_t)(m0 + wm * 32 + mi * 16 + qr) * 1024;
#pragma unroll
        for (int nj = 0; nj < 8; nj++) {
            int col = n0 + wn * 64 + nj * 8 + qc * 2;
            *(unsigned*)&C[r0 + col] =
                pack_h2(acc[mi][nj][0] * scale, acc[mi][nj][1] * scale);
            *(unsigned*)&C[r0 + 8 * 1024 + col] =
                pack_h2(acc[mi][nj][2] * scale, acc[mi][nj][3] * scale);
        }
    }
}

// Output projection: half in, fp32 out + bias
__global__ __launch_bounds__(256) void gemm_bias_kernel(
    const __half* __restrict__ A, const __half* __restrict__ W,
    float* __restrict__ C, const float* __restrict__ bias)
{
    extern __shared__ __half gsm[];
    const int m0 = blockIdx.y * 128, n0 = blockIdx.x * 128;
    const int warp = threadIdx.x >> 5, lane = threadIdx.x & 31;
    const int wm = warp >> 1, wn = warp & 1;
    const int qr = lane >> 2, qc = lane & 3;
    uint32_t sb = (uint32_t)__cvta_generic_to_shared(gsm);

    float acc[2][8][4];
#pragma unroll
    for (int mi = 0; mi < 2; mi++)
#pragma unroll
        for (int nj = 0; nj < 8; nj++)
#pragma unroll
            for (int e = 0; e < 4; e++) acc[mi][nj][e] = 0.0f;

    gemm_mainloop_raw(A, W, m0, n0, sb, acc);

#pragma unroll
    for (int mi = 0; mi < 2; mi++) {
        const size_t r0 = (size_t)(m0 + wm * 32 + mi * 16 + qr) * 1024;
#pragma unroll
        for (int nj = 0; nj < 8; nj++) {
            int col = n0 + wn * 64 + nj * 8 + qc * 2;
            float b0 = __ldg(&bias[col]), b1 = __ldg(&bias[col + 1]);
            float2 v0 = { acc[mi][nj][0] + b0, acc[mi][nj][1] + b1 };
            float2 v1 = { acc[mi][nj][2] + b0, acc[mi][nj][3] + b1 };
            *(float2*)&C[r0 + col] = v0;
            *(float2*)&C[r0 + 8 * 1024 + col] = v1;
        }
    }
}

// ---------------------------------------------------------------------------
// Flash attention v5 at (256, 2) (R15 config, unchanged).
// ---------------------------------------------------------------------------
#define AST 36864
#define AOFF_V 18432
#define AOFF_QTMP 36864
#define AOFF_LR  73728
#define ATTN_SMEM 74240

__global__ __launch_bounds__(256, 2) void attn_kernel(
    const __half* __restrict__ Q, const __half* __restrict__ K,
    const __half* __restrict__ V, __half* __restrict__ CTX)
{
    extern __shared__ char smraw[];
    float* l_red = (float*)(smraw + AOFF_LR);
    uint32_t sb = (uint32_t)__cvta_generic_to_shared(smraw);

    const int tid  = threadIdx.x;
    const int warp = tid >> 5;
    const int lane = tid & 31;
    const int wm   = warp >> 1;
    const int wk2  = warp & 1;
    const int qr   = lane >> 2;
    const int qc   = lane & 3;
    const int b    = blockIdx.y >> 4;
    const int h    = blockIdx.y & 15;
    const int s0   = blockIdx.x * 64;
    const size_t base = (size_t)b * SEQ * EMBED + (size_t)h * HDIM;

#pragma unroll
    for (int i = 0; i < 2; i++) {
        int idx = tid + i * 256;
        int row = idx >> 3;
        int c8  = (idx & 7) * 8;
        cp16(sb + AOFF_QTMP + (row * ALD + c8) * 2,
             &Q[base + (size_t)(s0 + row) * 1024 + c8]);
    }
#pragma unroll
    for (int i = 0; i < 4; i++) {
        int idx = tid + i * 256;
        int row = idx >> 3;
        int c8  = (idx & 7) * 8;
        cp16(sb + (row * ALD + c8) * 2,
             &K[base + (size_t)row * 1024 + c8]);
        cp16(sb + AOFF_V + (row * ALD + c8) * 2,
             &V[base + (size_t)row * 1024 + c8]);
    }
    CP_COMMIT();
    if (tid < 64) l_red[tid] = 0.0f;

    CP_WAIT(0);
    __syncthreads();

    uint32_t qf[4][4];
#pragma unroll
    for (int kd = 0; kd < 4; kd++)
        ldsm_x4(qf[kd], ldsm_addr(sb + AOFF_QTMP, wm * 16, kd * 16, lane));
    __syncthreads();

    float oacc[8][4];
#pragma unroll
    for (int i = 0; i < 8; i++)
#pragma unroll
        for (int e = 0; e < 4; e++) oacc[i][e] = 0.0f;
    float lsum0 = 0.0f, lsum1 = 0.0f;

    for (int j = 0; j < 16; j++) {
        if (j > 0) { CP_WAIT(0); __syncthreads(); }
        if (j < 15) {
            uint32_t st = ((j + 1) & 1) ? AST : 0u;
            const size_t gb = base + (size_t)((j + 1) * 128) * 1024;
#pragma unroll
            for (int i = 0; i < 4; i++) {
                int idx = tid + i * 256;
                int row = idx >> 3;
                int c8  = (idx & 7) * 8;
                cp16(sb + st + (row * ALD + c8) * 2,
                     &K[gb + (size_t)row * 1024 + c8]);
                cp16(sb + st + AOFF_V + (row * ALD + c8) * 2,
                     &V[gb + (size_t)row * 1024 + c8]);
            }
            CP_COMMIT();
        }

        const uint32_t bK = sb + ((j & 1) ? AST : 0u);
        const uint32_t bV = bK + AOFF_V;

#pragma unroll
        for (int h2 = 0; h2 < 2; h2++) {
            const int key0 = wk2 * 64 + h2 * 32;

            float sc[4][4];
#pragma unroll
            for (int i = 0; i < 4; i++)
#pragma unroll
                for (int e = 0; e < 4; e++) sc[i][e] = 0.0f;
#pragma unroll
            for (int kd = 0; kd < 4; kd++) {
#pragma unroll
                for (int kn = 0; kn < 2; kn++) {
                    uint32_t bf[4];
                    ldsm_x4(bf, ldsm_addr(bK, key0 + kn * 16, kd * 16, lane));
                    mma16816(sc[2 * kn],     qf[kd], bf[0], bf[2]);
                    mma16816(sc[2 * kn + 1], qf[kd], bf[1], bf[3]);
                }
            }

            uint32_t pf[2][4];
#pragma unroll
            for (int t = 0; t < 2; t++) {
                float e00 = ex2(sc[2*t][0]),   e01 = ex2(sc[2*t][1]);
                float e02 = ex2(sc[2*t][2]),   e03 = ex2(sc[2*t][3]);
                float e10 = ex2(sc[2*t+1][0]), e11 = ex2(sc[2*t+1][1]);
                float e12 = ex2(sc[2*t+1][2]), e13 = ex2(sc[2*t+1][3]);
                lsum0 += e00 + e01 + e10 + e11;
                lsum1 += e02 + e03 + e12 + e13;
                pf[t][0] = pack_h2(e00, e01);
                pf[t][1] = pack_h2(e02, e03);
                pf[t][2] = pack_h2(e10, e11);
                pf[t][3] = pack_h2(e12, e13);
            }

#pragma unroll
            for (int t = 0; t < 2; t++) {
#pragma unroll
                for (int dn = 0; dn < 4; dn++) {
                    uint32_t vf[4];
                    ldsm_x4_t(vf, ldsm_addr(bV, key0 + t * 16, dn * 16, lane));
                    mma16816(oacc[2 * dn],     pf[t], vf[0], vf[1]);
                    mma16816(oacc[2 * dn + 1], pf[t], vf[2], vf[3]);
                }
            }
        }
    }

    lsum0 += __shfl_xor_sync(0xffffffffu, lsum0, 1);
    lsum0 += __shfl_xor_sync(0xffffffffu, lsum0, 2);
    lsum1 += __shfl_xor_sync(0xffffffffu, lsum1, 1);
    lsum1 += __shfl_xor_sync(0xffffffffu, lsum1, 2);
    if (qc == 0) {
        atomicAdd(&l_red[wm * 16 + qr], lsum0);
        atomicAdd(&l_red[wm * 16 + qr + 8], lsum1);
    }
    __syncthreads();

    float* Cs = (float*)smraw;
    if (wk2 == 0) {
#pragma unroll
        for (int dn = 0; dn < 8; dn++) {
            int col = dn * 8 + qc * 2;
            Cs[(wm * 16 + qr) * 68 + col]         = oacc[dn][0];
            Cs[(wm * 16 + qr) * 68 + col + 1]     = oacc[dn][1];
            Cs[(wm * 16 + qr + 8) * 68 + col]     = oacc[dn][2];
            Cs[(wm * 16 + qr + 8) * 68 + col + 1] = oacc[dn][3];
        }
    }
    __syncthreads();
    if (wk2 == 1) {
#pragma unroll
        for (int dn = 0; dn < 8; dn++) {
            int col = dn * 8 + qc * 2;
            Cs[(wm * 16 + qr) * 68 + col]         += oacc[dn][0];
            Cs[(wm * 16 + qr) * 68 + col + 1]     += oacc[dn][1];
            Cs[(wm * 16 + qr + 8) * 68 + col]     += oacc[dn][2];
            Cs[(wm * 16 + qr + 8) * 68 + col + 1] += oacc[dn][3];
        }
    }
    __syncthreads();

#pragma unroll
    for (int i = 0; i < 2; i++) {
        int idx = tid + i * 256;
        int row = idx >> 3;
        int c8  = (idx & 7) * 8;
        float rl = __frcp_rn(l_red[row]);
        float4 v0 = *(float4*)&Cs[row * 68 + c8];
        float4 v1 = *(float4*)&Cs[row * 68 + c8 + 4];
        uint4 u;
        u.x = pack_h2(v0.x * rl, v0.y * rl);
        u.y = pack_h2(v0.z * rl, v0.w * rl);
        u.z = pack_h2(v1.x * rl, v1.y * rl);
        u.w = pack_h2(v1.z * rl, v1.w * rl);
        *(uint4*)&CTX[base + (size_t)(s0 + row) * 1024 + c8] = u;
    }
}

// ---------------------------------------------------------------------------
// Launch
// ---------------------------------------------------------------------------
extern "C" void kernel_launch(void* const* d_in, const int* in_sizes, int n_in,
                              void* d_out, int out_size)
{
    const float* key   = (const float*)d_in[0];
    const float* query = (const float*)d_in[1];
    const float* value = (const float*)d_in[2];
    const float* Wq    = (const float*)d_in[3];
    const float* Wk    = (const float*)d_in[4];
    const float* Wv    = (const float*)d_in[5];
    const float* Wo    = (const float*)d_in[6];
    const float* bo    = (const float*)d_in[7];
    float* out = (float*)d_out;

    __half *hXq, *hXk, *hXv, *hWq, *hWk, *hWv, *hWo, *hQ, *hK, *hV, *hCTX;
    cudaGetSymbolAddress((void**)&hXq, g_hXq);
    cudaGetSymbolAddress((void**)&hXk, g_hXk);
    cudaGetSymbolAddress((void**)&hXv, g_hXv);
    cudaGetSymbolAddress((void**)&hWq, g_hWq);
    cudaGetSymbolAddress((void**)&hWk, g_hWk);
    cudaGetSymbolAddress((void**)&hWv, g_hWv);
    cudaGetSymbolAddress((void**)&hWo, g_hWo);
    cudaGetSymbolAddress((void**)&hQ, g_hQ);
    cudaGetSymbolAddress((void**)&hK, g_hK);
    cudaGetSymbolAddress((void**)&hV, g_hV);
    cudaGetSymbolAddress((void**)&hCTX, g_hCTX);

    const int cvt_total = 3 * X4 + 4 * W4;
    cvt_all<<<cvt_total / 512, 256>>>(query, key, value, Wq, Wk, Wv, Wo,
                                      hXq, hXk, hXv, hWq, hWk, hWv, hWo);

    cudaFuncSetAttribute(proj3_kernel,
        cudaFuncAttributeMaxDynamicSharedMemorySize, GEMM_SMEM);
    cudaFuncSetAttribute(gemm_bias_kernel,
        cudaFuncAttributeMaxDynamicSharedMemorySize, GEMM_SMEM);
    cudaFuncSetAttribute(attn_kernel,
        cudaFuncAttributeMaxDynamicSharedMemorySize, ATTN_SMEM);

    dim3 proj_grid(EMBED / 128, MTOT / 128, 3);
    proj3_kernel<<<proj_grid, 256, GEMM_SMEM>>>(
        hXq, hXk, hXv, hWq, hWk, hWv, hQ, hK, hV);

    attn_kernel<<<dim3(SEQ / 64, BATCH * NHEADS), 256, ATTN_SMEM>>>(
        hQ, hK, hV, hCTX);

    gemm_bias_kernel<<<dim3(EMBED / 128, MTOT / 128), 256, GEMM_SMEM>>>(
        hCTX, hWo, out, bo);
}

// round 17
// speedup vs baseline: 1.0198x; 1.0198x over previous
#include <cuda_runtime.h>
#include <cuda_fp16.h>
#include <mma.h>
#include <cstdint>

using namespace nvcuda;

#define EMBED 1024
#define NHEADS 16
#define HDIM 64
#define BATCH 2
#define SEQ 2048
#define MTOT 4096

// fp16 scratch (device globals -- no runtime allocation allowed)
__device__ __half g_hXq[MTOT * EMBED];
__device__ __half g_hXk[MTOT * EMBED];
__device__ __half g_hXv[MTOT * EMBED];
__device__ __half g_hWq[EMBED * EMBED];
__device__ __half g_hWk[EMBED * EMBED];
__device__ __half g_hWv[EMBED * EMBED];
__device__ __half g_hWo[EMBED * EMBED];
__device__ __half g_hQ[MTOT * EMBED];
__device__ __half g_hK[MTOT * EMBED];
__device__ __half g_hV[MTOT * EMBED];
__device__ __half g_hCTX[MTOT * EMBED];

__device__ __forceinline__ void cp16(uint32_t dst, const void* src) {
    asm volatile("cp.async.cg.shared.global [%0], [%1], 16;\n"
                 :: "r"(dst), "l"(src));
}
#define CP_COMMIT() asm volatile("cp.async.commit_group;\n")
#define CP_WAIT(n)  asm volatile("cp.async.wait_group %0;\n" :: "n"(n))

__device__ __forceinline__ unsigned pack_h2(float a, float b) {
    __half2 h = __floats2half2_rn(a, b);
    return *(unsigned*)&h;
}

__device__ __forceinline__ float ex2(float x) {
    float r;
    asm("ex2.approx.f32 %0, %1;" : "=f"(r) : "f"(x));
    return r;
}

// ---- raw mma helpers ----
__device__ __forceinline__ void ldsm_x4(uint32_t* r, uint32_t addr) {
    asm volatile("ldmatrix.sync.aligned.m8n8.x4.shared.b16 {%0,%1,%2,%3}, [%4];"
        : "=r"(r[0]), "=r"(r[1]), "=r"(r[2]), "=r"(r[3]) : "r"(addr));
}
__device__ __forceinline__ void ldsm_x4_t(uint32_t* r, uint32_t addr) {
    asm volatile("ldmatrix.sync.aligned.m8n8.x4.trans.shared.b16 {%0,%1,%2,%3}, [%4];"
        : "=r"(r[0]), "=r"(r[1]), "=r"(r[2]), "=r"(r[3]) : "r"(addr));
}
__device__ __forceinline__ void mma16816(float* c, const uint32_t* a,
                                         uint32_t b0, uint32_t b1) {
    asm volatile(
        "mma.sync.aligned.m16n8k16.row.col.f32.f16.f16.f32 "
        "{%0,%1,%2,%3}, {%4,%5,%6,%7}, {%8,%9}, {%0,%1,%2,%3};"
        : "+f"(c[0]), "+f"(c[1]), "+f"(c[2]), "+f"(c[3])
        : "r"(a[0]), "r"(a[1]), "r"(a[2]), "r"(a[3]), "r"(b0), "r"(b1));
}

#define ALD 72
__device__ __forceinline__ uint32_t ldsm_addr(uint32_t base, int row0, int col0,
                                              int lane) {
    int g = lane >> 3, l = lane & 7;
    int r = row0 + ((g & 1) << 3) + l;
    int c = col0 + ((g >> 1) << 3);
    return base + (uint32_t)(r * ALD + c) * 2;
}

// ---------------------------------------------------------------------------
// fp32 -> fp16 conversion of inputs + weights (2 float4 per thread)
// ---------------------------------------------------------------------------
#define X4 1048576
#define W4 262144

__global__ void cvt_all(
    const float* __restrict__ xq, const float* __restrict__ xk,
    const float* __restrict__ xv,
    const float* __restrict__ wq, const float* __restrict__ wk,
    const float* __restrict__ wv, const float* __restrict__ wo,
    __half* hxq, __half* hxk, __half* hxv,
    __half* hwq, __half* hwk, __half* hwv, __half* hwo)
{
    int i0 = (blockIdx.x * blockDim.x + threadIdx.x) * 2;
    const float* src; __half* dst; int off;
    if      (i0 < X4)            { src = xq; dst = hxq; off = i0; }
    else if (i0 < 2 * X4)        { src = xk; dst = hxk; off = i0 - X4; }
    else if (i0 < 3 * X4)        { src = xv; dst = hxv; off = i0 - 2 * X4; }
    else if (i0 < 3 * X4 + W4)   { src = wq; dst = hwq; off = i0 - 3 * X4; }
    else if (i0 < 3 * X4 + 2*W4) { src = wk; dst = hwk; off = i0 - 3*X4 - W4; }
    else if (i0 < 3 * X4 + 3*W4) { src = wv; dst = hwv; off = i0 - 3*X4 - 2*W4; }
    else                         { src = wo; dst = hwo; off = i0 - 3*X4 - 3*W4; }
#pragma unroll
    for (int t = 0; t < 2; t++) {
        float4 v = ((const float4*)src)[off + t];
        uint2 u;
        u.x = pack_h2(v.x, v.y); u.y = pack_h2(v.z, v.w);
        ((uint2*)dst)[off + t] = u;
    }
}

// ---------------------------------------------------------------------------
// GEMM (wmma, R10/R15 proven config): 128x128 tile, K-tile 64, 3-stage ring.
// ---------------------------------------------------------------------------
#define GLD 72
#define GSTAGE (2 * 128 * GLD)
#define GEMM_SMEM (3 * GSTAGE * 2)       // 110592 B

using AccFrag = wmma::fragment<wmma::accumulator, 16, 16, 16, float>;

__device__ __forceinline__ void gemm_fill(
    const __half* __restrict__ A, const __half* __restrict__ W,
    int m0, int n0, uint32_t sb, int s, int kt, int tid)
{
    int so = s * GSTAGE;
#pragma unroll
    for (int i = 0; i < 4; i++) {
        int idx = tid + i * 256;
        int row = idx >> 3;
        int c8  = (idx & 7) * 8;
        cp16(sb + (so + row * GLD + c8) * 2,
             &A[(size_t)(m0 + row) * 1024 + kt + c8]);
        cp16(sb + (so + 128 * GLD + row * GLD + c8) * 2,
             &W[(size_t)(n0 + row) * 1024 + kt + c8]);
    }
    CP_COMMIT();
}

__device__ __forceinline__ void gemm_mainloop(
    const __half* __restrict__ A, const __half* __restrict__ W,
    int m0, int n0, __half* smem, AccFrag acc[2][4])
{
    const int tid  = threadIdx.x;
    const int warp = tid >> 5;
    const int wm   = warp >> 1;
    const int wn   = warp & 1;
    uint32_t sb = (uint32_t)__cvta_generic_to_shared(smem);

    gemm_fill(A, W, m0, n0, sb, 0, 0, tid);
    gemm_fill(A, W, m0, n0, sb, 1, 64, tid);

    for (int t = 0; t < 16; t++) {
        if (t < 15) { CP_WAIT(1); } else { CP_WAIT(0); }
        __syncthreads();
        if (t + 2 <= 15)
            gemm_fill(A, W, m0, n0, sb, (t + 2) % 3, (t + 2) * 64, tid);

        const __half* As = smem + (t % 3) * GSTAGE;
        const __half* Bs = As + 128 * GLD;
#pragma unroll
        for (int kk = 0; kk < 64; kk += 16) {
            wmma::fragment<wmma::matrix_a, 16, 16, 16, __half,
                           wmma::row_major> a[2];
#pragma unroll
            for (int fm = 0; fm < 2; fm++)
                wmma::load_matrix_sync(a[fm],
                    &As[(wm * 32 + fm * 16) * GLD + kk], GLD);
#pragma unroll
            for (int fn = 0; fn < 4; fn++) {
                wmma::fragment<wmma::matrix_b, 16, 16, 16, __half,
                               wmma::col_major> b;
                wmma::load_matrix_sync(b,
                    &Bs[(wn * 64 + fn * 16) * GLD + kk], GLD);
#pragma unroll
                for (int fm = 0; fm < 2; fm++)
                    wmma::mma_sync(acc[fm][fn], a[fm], b, acc[fm][fn]);
            }
        }
    }
    __syncthreads();
}

__global__ __launch_bounds__(256) void proj3_kernel(
    const __half* __restrict__ xq, const __half* __restrict__ xk,
    const __half* __restrict__ xv,
    const __half* __restrict__ wq, const __half* __restrict__ wk,
    const __half* __restrict__ wv,
    __half* q, __half* k, __half* v)
{
    extern __shared__ __half gsm[];
    const __half* A; const __half* W; __half* C; float scale;
    if (blockIdx.z == 0)      { A = xq; W = wq; C = q; scale = 0.125f * 1.44269504f; }
    else if (blockIdx.z == 1) { A = xk; W = wk; C = k; scale = 1.0f; }
    else                      { A = xv; W = wv; C = v; scale = 1.0f; }
    const int m0 = blockIdx.y * 128, n0 = blockIdx.x * 128;
    const int tid = threadIdx.x, warp = tid >> 5, wm = warp >> 1, wn = warp & 1;

    AccFrag acc[2][4];
#pragma unroll
    for (int i = 0; i < 2; i++)
#pragma unroll
        for (int j = 0; j < 4; j++) wmma::fill_fragment(acc[i][j], 0.0f);

    gemm_mainloop(A, W, m0, n0, gsm, acc);

    float* Cs = (float*)gsm;
#pragma unroll
    for (int fm = 0; fm < 2; fm++)
#pragma unroll
        for (int fn = 0; fn < 4; fn++)
            wmma::store_matrix_sync(
                &Cs[(wm * 32 + fm * 16) * 128 + wn * 64 + fn * 16],
                acc[fm][fn], 128, wmma::mem_row_major);
    __syncthreads();
#pragma unroll
    for (int i = 0; i < 8; i++) {
        int idx = tid + i * 256;
        int row = idx >> 4;
        int c8  = (idx & 15) * 8;
        float4 v0 = *(float4*)&Cs[row * 128 + c8];
        float4 v1 = *(float4*)&Cs[row * 128 + c8 + 4];
        uint4 u;
        u.x = pack_h2(v0.x * scale, v0.y * scale);
        u.y = pack_h2(v0.z * scale, v0.w * scale);
        u.z = pack_h2(v1.x * scale, v1.y * scale);
        u.w = pack_h2(v1.z * scale, v1.w * scale);
        *(uint4*)&C[(size_t)(m0 + row) * 1024 + n0 + c8] = u;
    }
}

__global__ __launch_bounds__(256) void gemm_bias_kernel(
    const __half* __restrict__ A, const __half* __restrict__ W,
    float* __restrict__ C, const float* __restrict__ bias)
{
    extern __shared__ __half gsm[];
    __shared__ float biass[128];
    const int m0 = blockIdx.y * 128, n0 = blockIdx.x * 128;
    const int tid = threadIdx.x, warp = tid >> 5, wm = warp >> 1, wn = warp & 1;
    if (tid < 128) biass[tid] = bias[n0 + tid];

    AccFrag acc[2][4];
#pragma unroll
    for (int i = 0; i < 2; i++)
#pragma unroll
        for (int j = 0; j < 4; j++) wmma::fill_fragment(acc[i][j], 0.0f);

    gemm_mainloop(A, W, m0, n0, gsm, acc);

    float* Cs = (float*)gsm;
#pragma unroll
    for (int fm = 0; fm < 2; fm++)
#pragma unroll
        for (int fn = 0; fn < 4; fn++)
            wmma::store_matrix_sync(
                &Cs[(wm * 32 + fm * 16) * 132 + wn * 64 + fn * 16],
                acc[fm][fn], 132, wmma::mem_row_major);
    __syncthreads();
#pragma unroll
    for (int i = 0; i < 16; i++) {
        int idx = tid + i * 256;
        int row = idx >> 5;
        int col = (idx & 31) * 4;
        float4 v = *(float4*)&Cs[row * 132 + col];
        v.x += biass[col];     v.y += biass[col + 1];
        v.z += biass[col + 2]; v.w += biass[col + 3];
        *(float4*)&C[(size_t)(m0 + row) * 1024 + n0 + col] = v;
    }
}

// ---------------------------------------------------------------------------
// Flash attention v6: 128-row Q tiles, 8 warps each owning 16 FULL rows
// (no key split). Halves K/V global traffic per output row; row sums and
// final O scaling stay entirely in registers -- no epilogue barriers/atomics.
// ---------------------------------------------------------------------------
#define AQ_BYTES 18432                  // 128 x 72 half
#define AKV 18432                       // one K or V tile
#define AOFF_K0 18432
#define AOFF_V0 36864
#define AOFF_K1 55296
#define AOFF_V1 73728
#define ATTN_SMEM 92160                 // 90 KB -> 2 CTAs/SM

__global__ __launch_bounds__(256) void attn_kernel(
    const __half* __restrict__ Q, const __half* __restrict__ K,
    const __half* __restrict__ V, __half* __restrict__ CTX)
{
    extern __shared__ char smraw[];
    uint32_t sb = (uint32_t)__cvta_generic_to_shared(smraw);

    const int tid  = threadIdx.x;
    const int warp = tid >> 5;           // 0..7 -> rows warp*16
    const int lane = tid & 31;
    const int qr   = lane >> 2;
    const int qc   = lane & 3;
    const int b    = blockIdx.y >> 4;
    const int h    = blockIdx.y & 15;
    const int s0   = blockIdx.x * 128;
    const size_t base = (size_t)b * SEQ * EMBED + (size_t)h * HDIM;

    // Q (128 rows) + K(0) + V(0)
#pragma unroll
    for (int i = 0; i < 4; i++) {
        int idx = tid + i * 256;          // 0..1023
        int row = idx >> 3;               // 0..127
        int c8  = (idx & 7) * 8;
        cp16(sb + (row * ALD + c8) * 2,
             &Q[base + (size_t)(s0 + row) * 1024 + c8]);
        cp16(sb + AOFF_K0 + (row * ALD + c8) * 2,
             &K[base + (size_t)row * 1024 + c8]);
        cp16(sb + AOFF_V0 + (row * ALD + c8) * 2,
             &V[base + (size_t)row * 1024 + c8]);
    }
    CP_COMMIT();
    CP_WAIT(0);
    __syncthreads();

    // preload this warp's Q fragments (rows warp*16, d = 0..63)
    uint32_t qf[4][4];
#pragma unroll
    for (int kd = 0; kd < 4; kd++)
        ldsm_x4(qf[kd], ldsm_addr(sb, warp * 16, kd * 16, lane));
    // Q smem region is never overwritten -> no extra sync needed

    float oacc[8][4];
#pragma unroll
    for (int i = 0; i < 8; i++)
#pragma unroll
        for (int e = 0; e < 4; e++) oacc[i][e] = 0.0f;
    float lsum0 = 0.0f, lsum1 = 0.0f;     // rows qr, qr+8 of this warp's tile

    for (int j = 0; j < 16; j++) {
        if (j > 0) { CP_WAIT(0); __syncthreads(); }
        if (j < 15) {
            uint32_t offK = ((j + 1) & 1) ? AOFF_K1 : AOFF_K0;
            uint32_t offV = ((j + 1) & 1) ? AOFF_V1 : AOFF_V0;
            const size_t gb = base + (size_t)((j + 1) * 128) * 1024;
#pragma unroll
            for (int i = 0; i < 4; i++) {
                int idx = tid + i * 256;
                int row = idx >> 3;
                int c8  = (idx & 7) * 8;
                cp16(sb + offK + (row * ALD + c8) * 2,
                     &K[gb + (size_t)row * 1024 + c8]);
                cp16(sb + offV + (row * ALD + c8) * 2,
                     &V[gb + (size_t)row * 1024 + c8]);
            }
            CP_COMMIT();
        }

        const uint32_t bK = sb + ((j & 1) ? AOFF_K1 : AOFF_K0);
        const uint32_t bV = sb + ((j & 1) ? AOFF_V1 : AOFF_V0);

        // 4 chunks of 32 keys, full 128-key block per warp
#pragma unroll
        for (int h2 = 0; h2 < 4; h2++) {
            const int key0 = h2 * 32;

            float sc[4][4];
#pragma unroll
            for (int i = 0; i < 4; i++)
#pragma unroll
                for (int e = 0; e < 4; e++) sc[i][e] = 0.0f;
#pragma unroll
            for (int kd = 0; kd < 4; kd++) {
#pragma unroll
                for (int kn = 0; kn < 2; kn++) {
                    uint32_t bf[4];
                    ldsm_x4(bf, ldsm_addr(bK, key0 + kn * 16, kd * 16, lane));
                    mma16816(sc[2 * kn],     qf[kd], bf[0], bf[2]);
                    mma16816(sc[2 * kn + 1], qf[kd], bf[1], bf[3]);
                }
            }

            uint32_t pf[2][4];
#pragma unroll
            for (int t = 0; t < 2; t++) {
                float e00 = ex2(sc[2*t][0]),   e01 = ex2(sc[2*t][1]);
                float e02 = ex2(sc[2*t][2]),   e03 = ex2(sc[2*t][3]);
                float e10 = ex2(sc[2*t+1][0]), e11 = ex2(sc[2*t+1][1]);
                float e12 = ex2(sc[2*t+1][2]), e13 = ex2(sc[2*t+1][3]);
                lsum0 += e00 + e01 + e10 + e11;
                lsum1 += e02 + e03 + e12 + e13;
                pf[t][0] = pack_h2(e00, e01);
                pf[t][1] = pack_h2(e02, e03);
                pf[t][2] = pack_h2(e10, e11);
                pf[t][3] = pack_h2(e12, e13);
            }

#pragma unroll
            for (int t = 0; t < 2; t++) {
#pragma unroll
                for (int dn = 0; dn < 4; dn++) {
                    uint32_t vf[4];
                    ldsm_x4_t(vf, ldsm_addr(bV, key0 + t * 16, dn * 16, lane));
                    mma16816(oacc[2 * dn],     pf[t], vf[0], vf[1]);
                    mma16816(oacc[2 * dn + 1], pf[t], vf[2], vf[3]);
                }
            }
        }
    }

    // row sums complete within warp: quad reduce, all quad lanes get total
    lsum0 += __shfl_xor_sync(0xffffffffu, lsum0, 1);
    lsum0 += __shfl_xor_sync(0xffffffffu, lsum0, 2);
    lsum1 += __shfl_xor_sync(0xffffffffu, lsum1, 1);
    lsum1 += __shfl_xor_sync(0xffffffffu, lsum1, 2);
    const float rl0 = __frcp_rn(lsum0);
    const float rl1 = __frcp_rn(lsum1);

    // direct register -> global epilogue (half pairs)
    const size_t r0 = base + (size_t)(s0 + warp * 16 + qr) * 1024;
#pragma unroll
    for (int dn = 0; dn < 8; dn++) {
        int col = dn * 8 + qc * 2;
        *(unsigned*)&CTX[r0 + col] =
            pack_h2(oacc[dn][0] * rl0, oacc[dn][1] * rl0);
        *(unsigned*)&CTX[r0 + 8 * 1024 + col] =
            pack_h2(oacc[dn][2] * rl1, oacc[dn][3] * rl1);
    }
}

// ---------------------------------------------------------------------------
// Launch
// ---------------------------------------------------------------------------
extern "C" void kernel_launch(void* const* d_in, const int* in_sizes, int n_in,
                              void* d_out, int out_size)
{
    const float* key   = (const float*)d_in[0];
    const float* query = (const float*)d_in[1];
    const float* value = (const float*)d_in[2];
    const float* Wq    = (const float*)d_in[3];
    const float* Wk    = (const float*)d_in[4];
    const float* Wv    = (const float*)d_in[5];
    const float* Wo    = (const float*)d_in[6];
    const float* bo    = (const float*)d_in[7];
    float* out = (float*)d_out;

    __half *hXq, *hXk, *hXv, *hWq, *hWk, *hWv, *hWo, *hQ, *hK, *hV, *hCTX;
    cudaGetSymbolAddress((void**)&hXq, g_hXq);
    cudaGetSymbolAddress((void**)&hXk, g_hXk);
    cudaGetSymbolAddress((void**)&hXv, g_hXv);
    cudaGetSymbolAddress((void**)&hWq, g_hWq);
    cudaGetSymbolAddress((void**)&hWk, g_hWk);
    cudaGetSymbolAddress((void**)&hWv, g_hWv);
    cudaGetSymbolAddress((void**)&hWo, g_hWo);
    cudaGetSymbolAddress((void**)&hQ, g_hQ);
    cudaGetSymbolAddress((void**)&hK, g_hK);
    cudaGetSymbolAddress((void**)&hV, g_hV);
    cudaGetSymbolAddress((void**)&hCTX, g_hCTX);

    const int cvt_total = 3 * X4 + 4 * W4;
    cvt_all<<<cvt_total / 512, 256>>>(query, key, value, Wq, Wk, Wv, Wo,
                                      hXq, hXk, hXv, hWq, hWk, hWv, hWo);

    cudaFuncSetAttribute(proj3_kernel,
        cudaFuncAttributeMaxDynamicSharedMemorySize, GEMM_SMEM);
    cudaFuncSetAttribute(gemm_bias_kernel,
        cudaFuncAttributeMaxDynamicSharedMemorySize, GEMM_SMEM);
    cudaFuncSetAttribute(attn_kernel,
        cudaFuncAttributeMaxDynamicSharedMemorySize, ATTN_SMEM);

    dim3 proj_grid(EMBED / 128, MTOT / 128, 3);
    proj3_kernel<<<proj_grid, 256, GEMM_SMEM>>>(
        hXq, hXk, hXv, hWq, hWk, hWv, hQ, hK, hV);

    attn_kernel<<<dim3(SEQ / 128, BATCH * NHEADS), 256, ATTN_SMEM>>>(
        hQ, hK, hV, hCTX);

    gemm_bias_kernel<<<dim3(EMBED / 128, MTOT / 128), 256, GEMM_SMEM>>>(
        hCTX, hWo, out, bo);
}